// round 16
// baseline (speedup 1.0000x reference)
#include <cuda_runtime.h>
#include <cuda_fp16.h>
#include <cstdint>

// Problem constants
#define Bq   8
#define Sq   2048
#define Dq   1024
#define Hq   16
#define DHq  64
#define Mrows (Bq*Sq)        // 16384
#define BHn   (Bq*Hq)        // 128
#define OUT_MAIN (Mrows*Dq)  // 16777216 floats of `outputs`

__device__ float g_Tq[Mrows*32];
__device__ float g_Tk[Mrows*32];
__device__ float g_VV[BHn*DHq*DHq];
__device__ float g_VVV[Mrows*Dq];
__device__ float g_O1[Mrows*Dq];
__device__ float g_O2[Mrows*Dq];
__device__ float g_L [BHn*DHq];
__device__ float g_W2Aq[32*Dq];
__device__ float g_W2Ak[32*Dq];

// fp16 buffers
__device__ __align__(128) __half g_Ah [Mrows*Dq];
__device__ __align__(128) __half g_Vh [Mrows*Dq];
__device__ __align__(128) __half g_Bh [Dq*Dq];
__device__ __align__(128) __half g_Bh2[Dq*Dq];

// ===========================================================================
// PTX helpers
// ===========================================================================
__device__ __forceinline__ uint32_t smem_u32(const void* p) {
    uint32_t a;
    asm("{ .reg .u64 t; cvta.to.shared.u64 t, %1; cvt.u32.u64 %0, t; }" : "=r"(a) : "l"(p));
    return a;
}
__device__ __forceinline__ void cpa16(uint32_t s, const void* g) {
    asm volatile("cp.async.cg.shared.global [%0], [%1], 16;" :: "r"(s), "l"(g));
}
__device__ __forceinline__ void cpa_commit() {
    asm volatile("cp.async.commit_group;" ::: "memory");
}
__device__ __forceinline__ void cpa_wait1() {
    asm volatile("cp.async.wait_group 1;" ::: "memory");
}
__device__ __forceinline__ void ldsm4(uint32_t* r, uint32_t addr) {
    asm volatile("ldmatrix.sync.aligned.m8n8.x4.shared.b16 {%0,%1,%2,%3}, [%4];"
                 : "=r"(r[0]), "=r"(r[1]), "=r"(r[2]), "=r"(r[3]) : "r"(addr));
}
__device__ __forceinline__ void mma16816(float* c, const uint32_t* a, const uint32_t* b) {
    asm volatile(
        "mma.sync.aligned.m16n8k16.row.col.f32.f16.f16.f32 "
        "{%0,%1,%2,%3}, {%4,%5,%6,%7}, {%8,%9}, {%0,%1,%2,%3};"
        : "+f"(c[0]), "+f"(c[1]), "+f"(c[2]), "+f"(c[3])
        : "r"(a[0]), "r"(a[1]), "r"(a[2]), "r"(a[3]), "r"(b[0]), "r"(b[1]));
}

// ===========================================================================
// HMMA GEMM: 512 threads, 16 warps of 32x32, K-chunk 64, 3-stage / 1 sync.
// sel=0: B=g_Bh, out fp16 -> g_Vh.  sel=1: B=g_Bh2, out fp32 -> C.
// ===========================================================================
#define GP 72
#define ST_AH 0
#define ST_BH 18432
#define ST_BYTES 36864
#define HG_SMEM (3*ST_BYTES)

__device__ __forceinline__ void hg_load_stage(uint32_t sb, int st, const __half* gB,
                                              int m0, int n0, int kc, int tid) {
    uint32_t base = sb + st * ST_BYTES;
    #pragma unroll
    for (int i = 0; i < 2; i++) {
        int idx = tid + i * 512;
        int row = idx >> 3, c8 = idx & 7;
        uint32_t so = (uint32_t)(row * GP + c8 * 8) * 2;
        cpa16(base + ST_AH + so, g_Ah + (size_t)(m0 + row) * Dq + kc + c8 * 8);
        cpa16(base + ST_BH + so, gB   + (size_t)(n0 + row) * Dq + kc + c8 * 8);
    }
}

__global__ void __launch_bounds__(512) k_hgemm(float* __restrict__ C, int sel) {
    extern __shared__ char smem[];
    uint32_t sb = smem_u32(smem);
    const __half* gB = sel ? g_Bh2 : g_Bh;
    int tid = threadIdx.x;
    int lane = tid & 31, w = tid >> 5;
    int wm = w & 3, wn = w >> 2;
    int m0 = blockIdx.y * 128;
    int n0 = blockIdx.x * 128;

    float acc[2][4][4];
    #pragma unroll
    for (int i = 0; i < 2; i++)
        #pragma unroll
        for (int j = 0; j < 4; j++)
            #pragma unroll
            for (int k = 0; k < 4; k++) acc[i][j][k] = 0.f;

    hg_load_stage(sb, 0, gB, m0, n0, 0, tid);
    cpa_commit();
    hg_load_stage(sb, 1, gB, m0, n0, 64, tid);
    cpa_commit();

    int aRow = lane & 15, aKo = (lane >> 4) << 3;
    int bRow = (lane & 7) + ((lane >> 4) << 3);
    int bKo = ((lane >> 3) & 1) << 3;

    for (int c = 0; c < 16; c++) {
        cpa_wait1();
        __syncthreads();
        if (c + 2 < 16)
            hg_load_stage(sb, (c + 2) % 3, gB, m0, n0, (c + 2) * 64, tid);
        cpa_commit();
        uint32_t s0 = sb + (c % 3) * ST_BYTES;
        #pragma unroll
        for (int kh = 0; kh < 4; kh++) {
            uint32_t ah[2][4], bh[4][2];
            #pragma unroll
            for (int mt = 0; mt < 2; mt++) {
                uint32_t off = (uint32_t)((wm * 32 + mt * 16 + aRow) * GP + kh * 16 + aKo) * 2;
                ldsm4(ah[mt], s0 + ST_AH + off);
            }
            #pragma unroll
            for (int nt2 = 0; nt2 < 2; nt2++) {
                uint32_t off = (uint32_t)((wn * 32 + nt2 * 16 + bRow) * GP + kh * 16 + bKo) * 2;
                uint32_t r[4];
                ldsm4(r, s0 + ST_BH + off);
                bh[nt2*2][0] = r[0]; bh[nt2*2][1] = r[1];
                bh[nt2*2+1][0] = r[2]; bh[nt2*2+1][1] = r[3];
            }
            #pragma unroll
            for (int mt = 0; mt < 2; mt++)
                #pragma unroll
                for (int nt = 0; nt < 4; nt++) mma16816(acc[mt][nt], ah[mt], bh[nt]);
        }
    }

    if (sel == 0) {
        #pragma unroll
        for (int mt = 0; mt < 2; mt++) {
            int r0 = m0 + wm * 32 + mt * 16 + (lane >> 2);
            #pragma unroll
            for (int nt = 0; nt < 4; nt++) {
                int col = n0 + wn * 32 + nt * 8 + (lane & 3) * 2;
                *(__half2*)(g_Vh + (size_t)r0 * Dq + col) =
                    __floats2half2_rn(acc[mt][nt][0], acc[mt][nt][1]);
                *(__half2*)(g_Vh + (size_t)(r0 + 8) * Dq + col) =
                    __floats2half2_rn(acc[mt][nt][2], acc[mt][nt][3]);
            }
        }
    } else {
        #pragma unroll
        for (int mt = 0; mt < 2; mt++) {
            int r0 = m0 + wm * 32 + mt * 16 + (lane >> 2);
            #pragma unroll
            for (int nt = 0; nt < 4; nt++) {
                int col = n0 + wn * 32 + nt * 8 + (lane & 3) * 2;
                *(float2*)(C + (size_t)r0 * Dq + col)       = make_float2(acc[mt][nt][0], acc[mt][nt][1]);
                *(float2*)(C + (size_t)(r0 + 8) * Dq + col) = make_float2(acc[mt][nt][2], acc[mt][nt][3]);
            }
        }
    }
}

// ===========================================================================
// fp32 -> fp16 convert into g_Ah
// ===========================================================================
__global__ void k_half(const float* __restrict__ x) {
    size_t i = ((size_t)blockIdx.x * 256 + threadIdx.x) * 4;
    float4 v = *(const float4*)(x + i);
    *(__half2*)(g_Ah + i)     = __floats2half2_rn(v.x, v.y);
    *(__half2*)(g_Ah + i + 2) = __floats2half2_rn(v.z, v.w);
}

// ===========================================================================
// fp32 W[k][n] -> transposed fp16 Wt[n][k]
// ===========================================================================
__global__ void k_halfT(const float* __restrict__ W, int sel) {
    __shared__ float t[32][33];
    __half* dst = sel ? g_Bh2 : g_Bh;
    int tx = threadIdx.x, ty = threadIdx.y;
    int bx = blockIdx.x, by = blockIdx.y;
    #pragma unroll
    for (int i = 0; i < 4; i++)
        t[ty + i*8][tx] = W[(size_t)(by*32 + ty + i*8) * Dq + bx*32 + tx];
    __syncthreads();
    #pragma unroll
    for (int i = 0; i < 4; i++) {
        size_t o = (size_t)(bx*32 + ty + i*8) * Dq + by*32 + tx;
        dst[o] = __float2half(t[tx][ty + i*8]);
    }
}

// ===========================================================================
// prepW: fold A into the second projections.
// ===========================================================================
__global__ void k_prepW(const float* __restrict__ Wq2, const float* __restrict__ Wk2,
                        const float* __restrict__ Amat) {
    __shared__ float As[64][65];
    __shared__ float Wq[32][68];
    __shared__ float Wk[32][68];
    int h = blockIdx.x, t = threadIdx.x;
    for (int i = t; i < 4096; i += 256) {
        int f = i >> 6, d = i & 63;
        As[f][d] = Amat[i];
    }
    for (int i = t; i < 2048; i += 256) {
        int k = i >> 6, f = i & 63;
        Wq[k][f] = Wq2[(size_t)k * 1024 + h*64 + f];
        Wk[k][f] = Wk2[(size_t)k * 1024 + h*64 + f];
    }
    __syncthreads();
    int k = t >> 3, d0 = (t & 7) * 8;
    #pragma unroll
    for (int j = 0; j < 8; j++) {
        int d = d0 + j;
        float sq = 0.f, sk = 0.f;
        #pragma unroll
        for (int f = 0; f < 64; f++) {
            sq += Wq[k][f] * As[d][f];
            sk += Wk[k][f] * As[f][d];
        }
        g_W2Aq[(size_t)k * 1024 + h*64 + d] = sq;
        g_W2Ak[(size_t)k * 1024 + h*64 + d] = sk;
    }
}

// ---------------------------------------------------------------------------
// proj1 v4: T += X @ W1 over a 256-wide K slice. grid (4 ksplit, 256).
// ---------------------------------------------------------------------------
#define P1_XS 0
#define P1_WS 17408
#define P1_STAGE 26624
#define P1_SMEM (2*P1_STAGE)

__device__ __forceinline__ void p1_load(uint32_t sb, int st, const float* X,
                                        const float* W, int row0, int kc, int t) {
    uint32_t base = sb + st * P1_STAGE;
    #pragma unroll
    for (int i = 0; i < 4; i++) {
        int idx = t + i * 256;
        int r = idx >> 4, c4 = idx & 15;
        cpa16(base + P1_XS + (uint32_t)(r * 68 + c4 * 4) * 4,
              X + (size_t)(row0 + r) * 1024 + kc + c4 * 4);
    }
    #pragma unroll
    for (int i = 0; i < 2; i++) {
        int idx = t + i * 256;
        int k = idx >> 3, c4 = idx & 7;
        cpa16(base + P1_WS + (uint32_t)(k * 36 + c4 * 4) * 4,
              W + (size_t)(kc + k) * 32 + c4 * 4);
    }
}

__global__ void __launch_bounds__(256) k_proj1(const float* __restrict__ X,
                                               const float* __restrict__ W, int sel) {
    extern __shared__ char smem[];
    uint32_t sb = smem_u32(smem);
    float* T = sel ? g_Tk : g_Tq;
    int t = threadIdx.x;
    int row0 = blockIdx.y * 64;
    int k0 = blockIdx.x * 256;
    int tr = t >> 5, tc = t & 31;
    float acc[8] = {0.f,0.f,0.f,0.f,0.f,0.f,0.f,0.f};

    p1_load(sb, 0, X, W, row0, k0, t);
    cpa_commit();
    p1_load(sb, 1, X, W, row0, k0 + 64, t);
    cpa_commit();
    cpa_wait1();
    __syncthreads();

    for (int c = 0; c < 4; c++) {
        const float* Xs = (const float*)(smem + (c & 1) * P1_STAGE);
        const float* Ws = (const float*)(smem + (c & 1) * P1_STAGE + P1_WS);
        #pragma unroll
        for (int k = 0; k < 64; k += 4) {
            float w0 = Ws[k*36 + tc], w1 = Ws[(k+1)*36 + tc];
            float w2 = Ws[(k+2)*36 + tc], w3 = Ws[(k+3)*36 + tc];
            #pragma unroll
            for (int i = 0; i < 8; i++) {
                float4 x = *(const float4*)&Xs[(tr*8 + i) * 68 + k];
                acc[i] += x.x*w0 + x.y*w1 + x.z*w2 + x.w*w3;
            }
        }
        __syncthreads();
        if (c + 2 < 4) p1_load(sb, c & 1, X, W, row0, k0 + (c + 2) * 64, t);
        cpa_commit();
        cpa_wait1();
        __syncthreads();
    }
    #pragma unroll
    for (int i = 0; i < 8; i++)
        atomicAdd(&T[(size_t)(row0 + tr*8 + i) * 32 + tc], acc[i]);
}

// ---------------------------------------------------------------------------
// k_sum: scores1 = Tk @ W2Ak, exp, row sums -> g_L ONLY (no attn store).
// grid (32 sblk, 128 bh), 256 threads.
// ---------------------------------------------------------------------------
__global__ void k_sum() {
    __shared__ float Ts[64][33];
    __shared__ float Ws[32][68];
    __shared__ float wsum[8][16];
    int bh = blockIdx.y;
    int b = bh >> 4, h = bh & 15;
    int s0 = blockIdx.x * 64;
    int t = threadIdx.x;
    for (int i = t; i < 2048; i += 256) {
        int r = i >> 5, k = i & 31;
        Ts[r][k] = g_Tk[(size_t)(b * Sq + s0 + r) * 32 + k];
    }
    for (int i = t; i < 2048; i += 256) {
        int k = i >> 6, d = i & 63;
        Ws[k][d] = g_W2Ak[(size_t)k * 1024 + h*64 + d];
    }
    __syncthreads();
    int sl = t & 63, dg = t >> 6;
    float acc[16];
    #pragma unroll
    for (int i = 0; i < 16; i++) acc[i] = 0.f;
    #pragma unroll
    for (int k = 0; k < 32; k++) {
        float tk = Ts[sl][k];
        #pragma unroll
        for (int d4 = 0; d4 < 4; d4++) {
            float4 wv = *(const float4*)&Ws[k][dg*16 + d4*4];
            acc[d4*4]   += tk * wv.x;
            acc[d4*4+1] += tk * wv.y;
            acc[d4*4+2] += tk * wv.z;
            acc[d4*4+3] += tk * wv.w;
        }
    }
    #pragma unroll
    for (int dd = 0; dd < 16; dd++) {
        float v = __expf(acc[dd] * 0.125f);
        #pragma unroll
        for (int o = 16; o > 0; o >>= 1) v += __shfl_xor_sync(0xffffffffu, v, o);
        if ((t & 31) == 0) wsum[t >> 5][dd] = v;
    }
    __syncthreads();
    if (t < 64) {
        int dgg = t >> 4, dd = t & 15;
        atomicAdd(&g_L[bh*64 + dgg*16 + dd], wsum[dgg*2][dd] + wsum[dgg*2 + 1][dd]);
    }
}

// ---------------------------------------------------------------------------
// k_s1vv: recompute scores1 per tile, normalize (exp * 1/L), write attn ONCE,
// and accumulate VV = attn_n @ V into g_VV via atomicAdd.
// grid (4 ssplit, 128 bh), 256 threads.  ~42.8 KB static smem.
// ---------------------------------------------------------------------------
__global__ void __launch_bounds__(256) k_s1vv(float* __restrict__ attn) {
    __shared__ float Ts[64][33];   // Tk tile [s][k]
    __shared__ float Ws[32][68];   // W2Ak slice [k][d]
    __shared__ float At[64][65];   // normalized E [d][s]
    __shared__ __half Vs[64][68];  // V tile [s][f] fp16
    __shared__ float inv[64];
    int split = blockIdx.x;
    int bh = blockIdx.y;
    int b = bh >> 4, h = bh & 15;
    int t = threadIdx.x;
    int tr = t >> 4, tc = t & 15;
    int sl = t & 63, dg = t >> 6;
    if (t < 64) inv[t] = 1.f / g_L[bh*64 + t];
    for (int i = t; i < 2048; i += 256) {
        int k = i >> 6, d = i & 63;
        Ws[k][d] = g_W2Ak[(size_t)k * 1024 + h*64 + d];
    }
    __syncthreads();

    float acc[4][4];
    #pragma unroll
    for (int i = 0; i < 4; i++)
        #pragma unroll
        for (int j = 0; j < 4; j++) acc[i][j] = 0.f;

    int sbeg = split * 512;
    for (int sc0 = sbeg; sc0 < sbeg + 512; sc0 += 64) {
        // load Tk tile + V tile
        for (int i = t; i < 2048; i += 256) {
            int r = i >> 5, k = i & 31;
            Ts[r][k] = g_Tk[(size_t)(b * Sq + sc0 + r) * 32 + k];
        }
        for (int i = t; i < 4096; i += 256) {
            int ss = i >> 6, f = i & 63;
            Vs[ss][f] = g_Vh[(size_t)(b * Sq + sc0 + ss) * 1024 + h * 64 + f];
        }
        __syncthreads();
        // scores -> normalized E -> attn + At
        {
            float sac[16];
            #pragma unroll
            for (int i = 0; i < 16; i++) sac[i] = 0.f;
            #pragma unroll
            for (int k = 0; k < 32; k++) {
                float tk = Ts[sl][k];
                #pragma unroll
                for (int d4 = 0; d4 < 4; d4++) {
                    float4 wv = *(const float4*)&Ws[k][dg*16 + d4*4];
                    sac[d4*4]   += tk * wv.x;
                    sac[d4*4+1] += tk * wv.y;
                    sac[d4*4+2] += tk * wv.z;
                    sac[d4*4+3] += tk * wv.w;
                }
            }
            #pragma unroll
            for (int dd = 0; dd < 16; dd++) {
                int d = dg*16 + dd;
                float e = __expf(sac[dd] * 0.125f) * inv[d];
                attn[((size_t)(bh * 64 + d)) * Sq + sc0 + sl] = e;
                At[d][sl] = e;
            }
        }
        __syncthreads();
        // VV partial: At (64d x 64s) @ Vs (64s x 64f)
        #pragma unroll 8
        for (int ss = 0; ss < 64; ss++) {
            float av[4], bv[4];
            #pragma unroll
            for (int i = 0; i < 4; i++) av[i] = At[tr * 4 + i][ss];
            #pragma unroll
            for (int j = 0; j < 4; j++) bv[j] = __half2float(Vs[ss][tc * 4 + j]);
            #pragma unroll
            for (int i = 0; i < 4; i++)
                #pragma unroll
                for (int j = 0; j < 4; j++) acc[i][j] += av[i] * bv[j];
        }
        __syncthreads();
    }
    #pragma unroll
    for (int i = 0; i < 4; i++)
        #pragma unroll
        for (int j = 0; j < 4; j++)
            atomicAdd(&g_VV[(size_t)bh * 4096 + (tr * 4 + i) * 64 + tc * 4 + j], acc[i][j]);
}

// ---------------------------------------------------------------------------
// stage 2: scores2 = Tq @ W2Aq (fp32), fp32 softmax, P@VV via mma.
// ---------------------------------------------------------------------------
#define S2_TS   0
#define S2_WS   16896
#define S2_LINV 25600
#define S2_PH   26112
#define S2_VT   44544
#define S2_SMEM 53760

__global__ void __launch_bounds__(128) k_stage2() {
    extern __shared__ char smem[];
    uint32_t sb = smem_u32(smem);
    float* Ts   = (float*)(smem + S2_TS);
    float* Ws   = (float*)(smem + S2_WS);
    float* Linv = (float*)(smem + S2_LINV);
    __half* Ph  = (__half*)(smem + S2_PH);
    __half* Vt  = (__half*)(smem + S2_VT);
    int bh = blockIdx.y;
    int b = bh >> 4, h = bh & 15;
    int s0 = blockIdx.x * 128;
    int t = threadIdx.x, lane = t & 31, w = t >> 5;

    for (int i = t; i < 4096; i += 128) {
        int r = i >> 5, k = i & 31;
        Ts[r*33 + k] = g_Tq[(size_t)(b * Sq + s0 + r) * 32 + k];
    }
    for (int i = t; i < 2048; i += 128) {
        int k = i >> 6, d = i & 63;
        Ws[k*68 + d] = g_W2Aq[(size_t)k * 1024 + h*64 + d];
    }
    for (int i = t; i < 4096; i += 128) {
        int d = i >> 6, f = i & 63;
        Vt[f*72 + d] = __float2half(g_VV[(size_t)bh * 4096 + i]);
    }
    __syncthreads();

    {
        float sc[64];
        #pragma unroll
        for (int d = 0; d < 64; d++) sc[d] = 0.f;
        #pragma unroll
        for (int k = 0; k < 32; k++) {
            float tq = Ts[t*33 + k];
            #pragma unroll
            for (int d4 = 0; d4 < 16; d4++) {
                float4 wv = *(const float4*)&Ws[k*68 + d4*4];
                sc[d4*4]   += tq * wv.x;
                sc[d4*4+1] += tq * wv.y;
                sc[d4*4+2] += tq * wv.z;
                sc[d4*4+3] += tq * wv.w;
            }
        }
        float m = -1e30f;
        #pragma unroll
        for (int d = 0; d < 64; d++) { sc[d] *= 0.125f; m = fmaxf(m, sc[d]); }
        float l = 0.f;
        #pragma unroll
        for (int d = 0; d < 64; d++) { float e = __expf(sc[d] - m); sc[d] = e; l += e; }
        Linv[t] = 1.f / l;
        #pragma unroll
        for (int d = 0; d < 64; d++) Ph[t*72 + d] = __float2half(sc[d]);
    }
    __syncthreads();

    int aRow = lane & 15, aKo = (lane >> 4) << 3;
    int bRow = (lane & 7) + ((lane >> 4) << 3);
    int bKo = ((lane >> 3) & 1) << 3;
    {
        float acc[2][8][4];
        #pragma unroll
        for (int i = 0; i < 2; i++)
            #pragma unroll
            for (int j = 0; j < 8; j++)
                #pragma unroll
                for (int k = 0; k < 4; k++) acc[i][j][k] = 0.f;
        #pragma unroll
        for (int ks = 0; ks < 4; ks++) {
            uint32_t aq[2][4], bf[8][2];
            #pragma unroll
            for (int mt = 0; mt < 2; mt++)
                ldsm4(aq[mt], sb + S2_PH +
                      (uint32_t)((w*32 + mt*16 + aRow) * 72 + ks*16 + aKo) * 2);
            #pragma unroll
            for (int g = 0; g < 4; g++) {
                uint32_t r[4];
                ldsm4(r, sb + S2_VT + (uint32_t)((g*16 + bRow) * 72 + ks*16 + bKo) * 2);
                bf[g*2][0] = r[0]; bf[g*2][1] = r[1];
                bf[g*2+1][0] = r[2]; bf[g*2+1][1] = r[3];
            }
            #pragma unroll
            for (int mt = 0; mt < 2; mt++)
                #pragma unroll
                for (int nt = 0; nt < 8; nt++) mma16816(acc[mt][nt], aq[mt], bf[nt]);
        }
        #pragma unroll
        for (int mt = 0; mt < 2; mt++) {
            int r0 = w*32 + mt*16 + (lane >> 2);
            float inv0 = Linv[r0], inv1 = Linv[r0 + 8];
            float* O0 = g_VVV + ((size_t)bh * Sq + s0 + r0) * 64;
            float* O1 = g_VVV + ((size_t)bh * Sq + s0 + r0 + 8) * 64;
            #pragma unroll
            for (int nt = 0; nt < 8; nt++) {
                int c = nt*8 + (lane & 3) * 2;
                *(float2*)(O0 + c) = make_float2(acc[mt][nt][0] * inv0, acc[mt][nt][1] * inv0);
                *(float2*)(O1 + c) = make_float2(acc[mt][nt][2] * inv1, acc[mt][nt][3] * inv1);
            }
        }
    }
}

// ---------------------------------------------------------------------------
// LayerNorm (1024), vectorized float4.
// x = in1 + res.  sel=0: in1=g_VVV, res=Xq, out=g_O1 + fp16 g_Ah.
//                 sel=1: in1=g_O2,  res=g_O1, out=d_out.
// ---------------------------------------------------------------------------
__global__ void k_ln(const float* __restrict__ rese, const float* __restrict__ g,
                     const float* __restrict__ bb, float* __restrict__ oute, int sel) {
    const float* in1 = sel ? g_O2 : g_VVV;
    const float* res = sel ? g_O1 : rese;
    float* out = sel ? oute : g_O1;
    __shared__ float sm1[8];
    __shared__ float sm2[8];
    size_t base = (size_t)blockIdx.x * 1024;
    int t = threadIdx.x;
    int c = t * 4;
    float4 v = *(const float4*)(in1 + base + c);
    float4 r = *(const float4*)(res + base + c);
    v.x += r.x; v.y += r.y; v.z += r.z; v.w += r.w;
    float sum = v.x + v.y + v.z + v.w;
    #pragma unroll
    for (int o = 16; o > 0; o >>= 1) sum += __shfl_xor_sync(0xffffffffu, sum, o);
    if ((t & 31) == 0) sm1[t >> 5] = sum;
    __syncthreads();
    sum = 0.f;
    #pragma unroll
    for (int i = 0; i < 8; i++) sum += sm1[i];
    float mean = sum * (1.f / 1024.f);
    float dx = v.x - mean, dy = v.y - mean, dz = v.z - mean, dw = v.w - mean;
    float sq = dx*dx + dy*dy + dz*dz + dw*dw;
    #pragma unroll
    for (int o = 16; o > 0; o >>= 1) sq += __shfl_xor_sync(0xffffffffu, sq, o);
    if ((t & 31) == 0) sm2[t >> 5] = sq;
    __syncthreads();
    sq = 0.f;
    #pragma unroll
    for (int i = 0; i < 8; i++) sq += sm2[i];
    float rstd = rsqrtf(sq * (1.f / 1024.f) + 1e-5f);
    float4 gv = *(const float4*)(g + c);
    float4 bv = *(const float4*)(bb + c);
    float4 o4;
    o4.x = dx * rstd * gv.x + bv.x;
    o4.y = dy * rstd * gv.y + bv.y;
    o4.z = dz * rstd * gv.z + bv.z;
    o4.w = dw * rstd * gv.w + bv.w;
    *(float4*)(out + base + c) = o4;
    if (sel == 0) {
        *(__half2*)(g_Ah + base + c)     = __floats2half2_rn(o4.x, o4.y);
        *(__half2*)(g_Ah + base + c + 2) = __floats2half2_rn(o4.z, o4.w);
    }
}

// ===========================================================================
// Host side — single stream.
// ===========================================================================
extern "C" void kernel_launch(void* const* d_in, const int* in_sizes, int n_in,
                              void* d_out, int out_size) {
    const float* Xq  = (const float*)d_in[0];
    const float* Xk  = (const float*)d_in[1];
    const float* Xv  = (const float*)d_in[2];
    const float* Wq1 = (const float*)d_in[3];
    const float* Wq2 = (const float*)d_in[4];
    const float* Wk1 = (const float*)d_in[5];
    const float* Wk2 = (const float*)d_in[6];
    const float* Wv  = (const float*)d_in[7];
    const float* Wfc = (const float*)d_in[8];
    const float* Am  = (const float*)d_in[9];
    const float* lng = (const float*)d_in[10];
    const float* lnb = (const float*)d_in[11];
    float* out = (float*)d_out;
    size_t attn_off = (out_size > OUT_MAIN) ? (size_t)(out_size - OUT_MAIN) : 0;
    float* attn = out + attn_off;

    void *pO2, *pVV, *pL, *pTq, *pTk;
    cudaGetSymbolAddress(&pO2, g_O2);
    cudaGetSymbolAddress(&pVV, g_VV);
    cudaGetSymbolAddress(&pL,  g_L);
    cudaGetSymbolAddress(&pTq, g_Tq);
    cudaGetSymbolAddress(&pTk, g_Tk);

    cudaFuncSetAttribute(k_hgemm,  cudaFuncAttributeMaxDynamicSharedMemorySize, HG_SMEM);
    cudaFuncSetAttribute(k_proj1,  cudaFuncAttributeMaxDynamicSharedMemorySize, P1_SMEM);
    cudaFuncSetAttribute(k_stage2, cudaFuncAttributeMaxDynamicSharedMemorySize, S2_SMEM);

    k_half<<<16384, 256>>>(Xv);
    k_halfT<<<dim3(32, 32), dim3(32, 8)>>>(Wv, 0);
    k_prepW<<<16, 256>>>(Wq2, Wk2, Am);
    cudaMemsetAsync(pTq, 0, (size_t)Mrows * 32 * sizeof(float));
    cudaMemsetAsync(pTk, 0, (size_t)Mrows * 32 * sizeof(float));

    k_hgemm<<<dim3(8, 128), 512, HG_SMEM>>>(nullptr, 0);    // V -> g_Vh

    k_proj1<<<dim3(4, 256), 256, P1_SMEM>>>(Xq, Wq1, 0);
    k_proj1<<<dim3(4, 256), 256, P1_SMEM>>>(Xk, Wk1, 1);

    cudaMemsetAsync(pL,  0, (size_t)BHn * DHq * sizeof(float));
    cudaMemsetAsync(pVV, 0, (size_t)BHn * DHq * DHq * sizeof(float));
    k_sum<<<dim3(32, 128), 256>>>();                        // row sums only
    k_s1vv<<<dim3(4, 128), 256>>>(attn);                    // attn (1 write) + VV
    k_stage2<<<dim3(16, 128), 128, S2_SMEM>>>();
    k_ln<<<16384, 256>>>(Xq, lng, lnb, nullptr, 0);         // out1 + fp16

    k_halfT<<<dim3(32, 32), dim3(32, 8)>>>(Wfc, 1);
    k_hgemm<<<dim3(8, 128), 512, HG_SMEM>>>((float*)pO2, 1);// out2 = out1@Wfc
    k_ln<<<16384, 256>>>(nullptr, lng, lnb, out, 1);        // out = LN(out2+out1)
}

// round 17
// speedup vs baseline: 1.0808x; 1.0808x over previous
#include <cuda_runtime.h>
#include <cuda_fp16.h>
#include <cstdint>

// Problem constants
#define Bq   8
#define Sq   2048
#define Dq   1024
#define Hq   16
#define DHq  64
#define Mrows (Bq*Sq)        // 16384
#define BHn   (Bq*Hq)        // 128
#define OUT_MAIN (Mrows*Dq)  // 16777216 floats of `outputs`

__device__ float g_Tq[Mrows*32];
__device__ float g_Tk[Mrows*32];
__device__ float g_VV[BHn*DHq*DHq];
__device__ float g_VVV[Mrows*Dq];
__device__ float g_O1[Mrows*Dq];
__device__ float g_O2[Mrows*Dq];
__device__ float g_L [BHn*DHq];
__device__ float g_W2Aq[32*Dq];
__device__ float g_W2Ak[32*Dq];

// fp16 buffers
__device__ __align__(128) __half g_Ah [Mrows*Dq];
__device__ __align__(128) __half g_Vh [Mrows*Dq];
__device__ __align__(128) __half g_Bh [Dq*Dq];
__device__ __align__(128) __half g_Bh2[Dq*Dq];

// ===========================================================================
// PTX helpers
// ===========================================================================
__device__ __forceinline__ uint32_t smem_u32(const void* p) {
    uint32_t a;
    asm("{ .reg .u64 t; cvta.to.shared.u64 t, %1; cvt.u32.u64 %0, t; }" : "=r"(a) : "l"(p));
    return a;
}
__device__ __forceinline__ void cpa16(uint32_t s, const void* g) {
    asm volatile("cp.async.cg.shared.global [%0], [%1], 16;" :: "r"(s), "l"(g));
}
__device__ __forceinline__ void cpa_commit() {
    asm volatile("cp.async.commit_group;" ::: "memory");
}
__device__ __forceinline__ void cpa_wait1() {
    asm volatile("cp.async.wait_group 1;" ::: "memory");
}
__device__ __forceinline__ void ldsm4(uint32_t* r, uint32_t addr) {
    asm volatile("ldmatrix.sync.aligned.m8n8.x4.shared.b16 {%0,%1,%2,%3}, [%4];"
                 : "=r"(r[0]), "=r"(r[1]), "=r"(r[2]), "=r"(r[3]) : "r"(addr));
}
__device__ __forceinline__ void mma16816(float* c, const uint32_t* a, const uint32_t* b) {
    asm volatile(
        "mma.sync.aligned.m16n8k16.row.col.f32.f16.f16.f32 "
        "{%0,%1,%2,%3}, {%4,%5,%6,%7}, {%8,%9}, {%0,%1,%2,%3};"
        : "+f"(c[0]), "+f"(c[1]), "+f"(c[2]), "+f"(c[3])
        : "r"(a[0]), "r"(a[1]), "r"(a[2]), "r"(a[3]), "r"(b[0]), "r"(b[1]));
}

// ===========================================================================
// HMMA GEMM: 512 threads, 16 warps of 32x32, K-chunk 64, 3-stage / 1 sync.
// sel=0: B=g_Bh, out fp16 -> g_Vh.  sel=1: B=g_Bh2, out fp32 -> C.
// ===========================================================================
#define GP 72
#define ST_AH 0
#define ST_BH 18432
#define ST_BYTES 36864
#define HG_SMEM (3*ST_BYTES)

__device__ __forceinline__ void hg_load_stage(uint32_t sb, int st, const __half* gB,
                                              int m0, int n0, int kc, int tid) {
    uint32_t base = sb + st * ST_BYTES;
    #pragma unroll
    for (int i = 0; i < 2; i++) {
        int idx = tid + i * 512;
        int row = idx >> 3, c8 = idx & 7;
        uint32_t so = (uint32_t)(row * GP + c8 * 8) * 2;
        cpa16(base + ST_AH + so, g_Ah + (size_t)(m0 + row) * Dq + kc + c8 * 8);
        cpa16(base + ST_BH + so, gB   + (size_t)(n0 + row) * Dq + kc + c8 * 8);
    }
}

__global__ void __launch_bounds__(512) k_hgemm(float* __restrict__ C, int sel) {
    extern __shared__ char smem[];
    uint32_t sb = smem_u32(smem);
    const __half* gB = sel ? g_Bh2 : g_Bh;
    int tid = threadIdx.x;
    int lane = tid & 31, w = tid >> 5;
    int wm = w & 3, wn = w >> 2;
    int m0 = blockIdx.y * 128;
    int n0 = blockIdx.x * 128;

    float acc[2][4][4];
    #pragma unroll
    for (int i = 0; i < 2; i++)
        #pragma unroll
        for (int j = 0; j < 4; j++)
            #pragma unroll
            for (int k = 0; k < 4; k++) acc[i][j][k] = 0.f;

    hg_load_stage(sb, 0, gB, m0, n0, 0, tid);
    cpa_commit();
    hg_load_stage(sb, 1, gB, m0, n0, 64, tid);
    cpa_commit();

    int aRow = lane & 15, aKo = (lane >> 4) << 3;
    int bRow = (lane & 7) + ((lane >> 4) << 3);
    int bKo = ((lane >> 3) & 1) << 3;

    for (int c = 0; c < 16; c++) {
        cpa_wait1();
        __syncthreads();
        if (c + 2 < 16)
            hg_load_stage(sb, (c + 2) % 3, gB, m0, n0, (c + 2) * 64, tid);
        cpa_commit();
        uint32_t s0 = sb + (c % 3) * ST_BYTES;
        #pragma unroll
        for (int kh = 0; kh < 4; kh++) {
            uint32_t ah[2][4], bh[4][2];
            #pragma unroll
            for (int mt = 0; mt < 2; mt++) {
                uint32_t off = (uint32_t)((wm * 32 + mt * 16 + aRow) * GP + kh * 16 + aKo) * 2;
                ldsm4(ah[mt], s0 + ST_AH + off);
            }
            #pragma unroll
            for (int nt2 = 0; nt2 < 2; nt2++) {
                uint32_t off = (uint32_t)((wn * 32 + nt2 * 16 + bRow) * GP + kh * 16 + bKo) * 2;
                uint32_t r[4];
                ldsm4(r, s0 + ST_BH + off);
                bh[nt2*2][0] = r[0]; bh[nt2*2][1] = r[1];
                bh[nt2*2+1][0] = r[2]; bh[nt2*2+1][1] = r[3];
            }
            #pragma unroll
            for (int mt = 0; mt < 2; mt++)
                #pragma unroll
                for (int nt = 0; nt < 4; nt++) mma16816(acc[mt][nt], ah[mt], bh[nt]);
        }
    }

    if (sel == 0) {
        #pragma unroll
        for (int mt = 0; mt < 2; mt++) {
            int r0 = m0 + wm * 32 + mt * 16 + (lane >> 2);
            #pragma unroll
            for (int nt = 0; nt < 4; nt++) {
                int col = n0 + wn * 32 + nt * 8 + (lane & 3) * 2;
                *(__half2*)(g_Vh + (size_t)r0 * Dq + col) =
                    __floats2half2_rn(acc[mt][nt][0], acc[mt][nt][1]);
                *(__half2*)(g_Vh + (size_t)(r0 + 8) * Dq + col) =
                    __floats2half2_rn(acc[mt][nt][2], acc[mt][nt][3]);
            }
        }
    } else {
        #pragma unroll
        for (int mt = 0; mt < 2; mt++) {
            int r0 = m0 + wm * 32 + mt * 16 + (lane >> 2);
            #pragma unroll
            for (int nt = 0; nt < 4; nt++) {
                int col = n0 + wn * 32 + nt * 8 + (lane & 3) * 2;
                *(float2*)(C + (size_t)r0 * Dq + col)       = make_float2(acc[mt][nt][0], acc[mt][nt][1]);
                *(float2*)(C + (size_t)(r0 + 8) * Dq + col) = make_float2(acc[mt][nt][2], acc[mt][nt][3]);
            }
        }
    }
}

// ===========================================================================
// fp32 -> fp16 convert into g_Ah
// ===========================================================================
__global__ void k_half(const float* __restrict__ x) {
    size_t i = ((size_t)blockIdx.x * 256 + threadIdx.x) * 4;
    float4 v = *(const float4*)(x + i);
    *(__half2*)(g_Ah + i)     = __floats2half2_rn(v.x, v.y);
    *(__half2*)(g_Ah + i + 2) = __floats2half2_rn(v.z, v.w);
}

// ===========================================================================
// fp32 W[k][n] -> transposed fp16 Wt[n][k]
// ===========================================================================
__global__ void k_halfT(const float* __restrict__ W, int sel) {
    __shared__ float t[32][33];
    __half* dst = sel ? g_Bh2 : g_Bh;
    int tx = threadIdx.x, ty = threadIdx.y;
    int bx = blockIdx.x, by = blockIdx.y;
    #pragma unroll
    for (int i = 0; i < 4; i++)
        t[ty + i*8][tx] = W[(size_t)(by*32 + ty + i*8) * Dq + bx*32 + tx];
    __syncthreads();
    #pragma unroll
    for (int i = 0; i < 4; i++) {
        size_t o = (size_t)(bx*32 + ty + i*8) * Dq + by*32 + tx;
        dst[o] = __float2half(t[tx][ty + i*8]);
    }
}

// ===========================================================================
// prepW: fold A into the second projections.
// ===========================================================================
__global__ void k_prepW(const float* __restrict__ Wq2, const float* __restrict__ Wk2,
                        const float* __restrict__ Amat) {
    __shared__ float As[64][65];
    __shared__ float Wq[32][68];
    __shared__ float Wk[32][68];
    int h = blockIdx.x, t = threadIdx.x;
    for (int i = t; i < 4096; i += 256) {
        int f = i >> 6, d = i & 63;
        As[f][d] = Amat[i];
    }
    for (int i = t; i < 2048; i += 256) {
        int k = i >> 6, f = i & 63;
        Wq[k][f] = Wq2[(size_t)k * 1024 + h*64 + f];
        Wk[k][f] = Wk2[(size_t)k * 1024 + h*64 + f];
    }
    __syncthreads();
    int k = t >> 3, d0 = (t & 7) * 8;
    #pragma unroll
    for (int j = 0; j < 8; j++) {
        int d = d0 + j;
        float sq = 0.f, sk = 0.f;
        #pragma unroll
        for (int f = 0; f < 64; f++) {
            sq += Wq[k][f] * As[d][f];
            sk += Wk[k][f] * As[f][d];
        }
        g_W2Aq[(size_t)k * 1024 + h*64 + d] = sq;
        g_W2Ak[(size_t)k * 1024 + h*64 + d] = sk;
    }
}

// ---------------------------------------------------------------------------
// proj1 v4: T += X @ W1 over a 256-wide K slice. grid (4 ksplit, 256).
// ---------------------------------------------------------------------------
#define P1_XS 0
#define P1_WS 17408
#define P1_STAGE 26624
#define P1_SMEM (2*P1_STAGE)

__device__ __forceinline__ void p1_load(uint32_t sb, int st, const float* X,
                                        const float* W, int row0, int kc, int t) {
    uint32_t base = sb + st * P1_STAGE;
    #pragma unroll
    for (int i = 0; i < 4; i++) {
        int idx = t + i * 256;
        int r = idx >> 4, c4 = idx & 15;
        cpa16(base + P1_XS + (uint32_t)(r * 68 + c4 * 4) * 4,
              X + (size_t)(row0 + r) * 1024 + kc + c4 * 4);
    }
    #pragma unroll
    for (int i = 0; i < 2; i++) {
        int idx = t + i * 256;
        int k = idx >> 3, c4 = idx & 7;
        cpa16(base + P1_WS + (uint32_t)(k * 36 + c4 * 4) * 4,
              W + (size_t)(kc + k) * 32 + c4 * 4);
    }
}

__global__ void __launch_bounds__(256) k_proj1(const float* __restrict__ X,
                                               const float* __restrict__ W, int sel) {
    extern __shared__ char smem[];
    uint32_t sb = smem_u32(smem);
    float* T = sel ? g_Tk : g_Tq;
    int t = threadIdx.x;
    int row0 = blockIdx.y * 64;
    int k0 = blockIdx.x * 256;
    int tr = t >> 5, tc = t & 31;
    float acc[8] = {0.f,0.f,0.f,0.f,0.f,0.f,0.f,0.f};

    p1_load(sb, 0, X, W, row0, k0, t);
    cpa_commit();
    p1_load(sb, 1, X, W, row0, k0 + 64, t);
    cpa_commit();
    cpa_wait1();
    __syncthreads();

    for (int c = 0; c < 4; c++) {
        const float* Xs = (const float*)(smem + (c & 1) * P1_STAGE);
        const float* Ws = (const float*)(smem + (c & 1) * P1_STAGE + P1_WS);
        #pragma unroll
        for (int k = 0; k < 64; k += 4) {
            float w0 = Ws[k*36 + tc], w1 = Ws[(k+1)*36 + tc];
            float w2 = Ws[(k+2)*36 + tc], w3 = Ws[(k+3)*36 + tc];
            #pragma unroll
            for (int i = 0; i < 8; i++) {
                float4 x = *(const float4*)&Xs[(tr*8 + i) * 68 + k];
                acc[i] += x.x*w0 + x.y*w1 + x.z*w2 + x.w*w3;
            }
        }
        __syncthreads();
        if (c + 2 < 4) p1_load(sb, c & 1, X, W, row0, k0 + (c + 2) * 64, t);
        cpa_commit();
        cpa_wait1();
        __syncthreads();
    }
    #pragma unroll
    for (int i = 0; i < 8; i++)
        atomicAdd(&T[(size_t)(row0 + tr*8 + i) * 32 + tc], acc[i]);
}

// ---------------------------------------------------------------------------
// s1exp: scores1 = Tk @ W2Ak, exp, write E [bh,d,s] + row sums.
// ---------------------------------------------------------------------------
__global__ void k_s1exp(float* __restrict__ attn) {
    __shared__ float Ts[64][33];
    __shared__ float Ws[32][68];
    __shared__ float wsum[8][16];
    int bh = blockIdx.y;
    int b = bh >> 4, h = bh & 15;
    int s0 = blockIdx.x * 64;
    int t = threadIdx.x;
    for (int i = t; i < 2048; i += 256) {
        int r = i >> 5, k = i & 31;
        Ts[r][k] = g_Tk[(size_t)(b * Sq + s0 + r) * 32 + k];
    }
    for (int i = t; i < 2048; i += 256) {
        int k = i >> 6, d = i & 63;
        Ws[k][d] = g_W2Ak[(size_t)k * 1024 + h*64 + d];
    }
    __syncthreads();
    int sl = t & 63, dg = t >> 6;
    float acc[16];
    #pragma unroll
    for (int i = 0; i < 16; i++) acc[i] = 0.f;
    #pragma unroll
    for (int k = 0; k < 32; k++) {
        float tk = Ts[sl][k];
        #pragma unroll
        for (int d4 = 0; d4 < 4; d4++) {
            float4 wv = *(const float4*)&Ws[k][dg*16 + d4*4];
            acc[d4*4]   += tk * wv.x;
            acc[d4*4+1] += tk * wv.y;
            acc[d4*4+2] += tk * wv.z;
            acc[d4*4+3] += tk * wv.w;
        }
    }
    float es[16];
    #pragma unroll
    for (int dd = 0; dd < 16; dd++) {
        float e = __expf(acc[dd] * 0.125f);
        es[dd] = e;
        attn[((size_t)(bh * 64 + dg*16 + dd)) * Sq + s0 + sl] = e;
    }
    #pragma unroll
    for (int dd = 0; dd < 16; dd++) {
        float v = es[dd];
        #pragma unroll
        for (int o = 16; o > 0; o >>= 1) v += __shfl_xor_sync(0xffffffffu, v, o);
        if ((t & 31) == 0) wsum[t >> 5][dd] = v;
    }
    __syncthreads();
    if (t < 64) {
        int dgg = t >> 4, dd = t & 15;
        atomicAdd(&g_L[bh*64 + dgg*16 + dd], wsum[dgg*2][dd] + wsum[dgg*2 + 1][dd]);
    }
}

// ---------------------------------------------------------------------------
// vv v2: normalize attn in place and accumulate VV (V fp16).
// Vectorized: attn tiles via float4 LDG/STG, V tiles via uint4 LDG (8 halves)
// with in-register conversion; smem layouts unchanged (conflict-free).
// ---------------------------------------------------------------------------
__global__ void k_vv(float* __restrict__ attn) {
    __shared__ float At[64][65];
    __shared__ float Vs[64][65];
    __shared__ float inv[64];
    int split = blockIdx.x;
    int bh = blockIdx.y;
    int b = bh >> 4, h = bh & 15;
    int t = threadIdx.x;
    int tr = t >> 4, tc = t & 15;
    if (t < 64) inv[t] = 1.f / g_L[bh*64 + t];
    __syncthreads();
    float acc[4][4];
    #pragma unroll
    for (int i = 0; i < 4; i++)
        #pragma unroll
        for (int j = 0; j < 4; j++) acc[i][j] = 0.f;
    int sbeg = split * 512;
    for (int sc0 = sbeg; sc0 < sbeg + 512; sc0 += 64) {
        // attn tile: 64 d-rows x 64 s; 4 float4 per thread; normalize + write back
        #pragma unroll
        for (int i = 0; i < 4; i++) {
            int idx = t + i * 256;               // 0..1023
            int d = idx >> 4, s4 = (idx & 15) * 4;
            size_t gidx = ((size_t)(bh * 64 + d)) * Sq + sc0 + s4;
            float4 e4 = *(const float4*)(attn + gidx);
            float iv = inv[d];
            e4.x *= iv; e4.y *= iv; e4.z *= iv; e4.w *= iv;
            At[d][s4]     = e4.x;
            At[d][s4 + 1] = e4.y;
            At[d][s4 + 2] = e4.z;
            At[d][s4 + 3] = e4.w;
            *(float4*)(attn + gidx) = e4;
        }
        // V tile: 64 s-rows x 64 f halves; 2 uint4 per thread, convert to fp32
        #pragma unroll
        for (int i = 0; i < 2; i++) {
            int idx = t + i * 256;               // 0..511
            int ss = idx >> 3, c8 = (idx & 7) * 8;
            uint4 v8 = *(const uint4*)(g_Vh + (size_t)(b * Sq + sc0 + ss) * 1024 + h * 64 + c8);
            const __half2* hp = (const __half2*)&v8;
            #pragma unroll
            for (int j = 0; j < 4; j++) {
                float2 f = __half22float2(hp[j]);
                Vs[ss][c8 + j*2]     = f.x;
                Vs[ss][c8 + j*2 + 1] = f.y;
            }
        }
        __syncthreads();
        #pragma unroll 8
        for (int ss = 0; ss < 64; ss++) {
            float av[4], bv[4];
            #pragma unroll
            for (int i = 0; i < 4; i++) av[i] = At[tr * 4 + i][ss];
            #pragma unroll
            for (int j = 0; j < 4; j++) bv[j] = Vs[ss][tc * 4 + j];
            #pragma unroll
            for (int i = 0; i < 4; i++)
                #pragma unroll
                for (int j = 0; j < 4; j++) acc[i][j] += av[i] * bv[j];
        }
        __syncthreads();
    }
    #pragma unroll
    for (int i = 0; i < 4; i++)
        #pragma unroll
        for (int j = 0; j < 4; j++)
            atomicAdd(&g_VV[(size_t)bh * 4096 + (tr * 4 + i) * 64 + tc * 4 + j], acc[i][j]);
}

// ---------------------------------------------------------------------------
// stage 2: scores2 = Tq @ W2Aq (fp32), fp32 softmax, P@VV via mma.
// ---------------------------------------------------------------------------
#define S2_TS   0
#define S2_WS   16896
#define S2_LINV 25600
#define S2_PH   26112
#define S2_VT   44544
#define S2_SMEM 53760

__global__ void __launch_bounds__(128) k_stage2() {
    extern __shared__ char smem[];
    uint32_t sb = smem_u32(smem);
    float* Ts   = (float*)(smem + S2_TS);
    float* Ws   = (float*)(smem + S2_WS);
    float* Linv = (float*)(smem + S2_LINV);
    __half* Ph  = (__half*)(smem + S2_PH);
    __half* Vt  = (__half*)(smem + S2_VT);
    int bh = blockIdx.y;
    int b = bh >> 4, h = bh & 15;
    int s0 = blockIdx.x * 128;
    int t = threadIdx.x, lane = t & 31, w = t >> 5;

    for (int i = t; i < 4096; i += 128) {
        int r = i >> 5, k = i & 31;
        Ts[r*33 + k] = g_Tq[(size_t)(b * Sq + s0 + r) * 32 + k];
    }
    for (int i = t; i < 2048; i += 128) {
        int k = i >> 6, d = i & 63;
        Ws[k*68 + d] = g_W2Aq[(size_t)k * 1024 + h*64 + d];
    }
    for (int i = t; i < 4096; i += 128) {
        int d = i >> 6, f = i & 63;
        Vt[f*72 + d] = __float2half(g_VV[(size_t)bh * 4096 + i]);
    }
    __syncthreads();

    {
        float sc[64];
        #pragma unroll
        for (int d = 0; d < 64; d++) sc[d] = 0.f;
        #pragma unroll
        for (int k = 0; k < 32; k++) {
            float tq = Ts[t*33 + k];
            #pragma unroll
            for (int d4 = 0; d4 < 16; d4++) {
                float4 wv = *(const float4*)&Ws[k*68 + d4*4];
                sc[d4*4]   += tq * wv.x;
                sc[d4*4+1] += tq * wv.y;
                sc[d4*4+2] += tq * wv.z;
                sc[d4*4+3] += tq * wv.w;
            }
        }
        float m = -1e30f;
        #pragma unroll
        for (int d = 0; d < 64; d++) { sc[d] *= 0.125f; m = fmaxf(m, sc[d]); }
        float l = 0.f;
        #pragma unroll
        for (int d = 0; d < 64; d++) { float e = __expf(sc[d] - m); sc[d] = e; l += e; }
        Linv[t] = 1.f / l;
        #pragma unroll
        for (int d = 0; d < 64; d++) Ph[t*72 + d] = __float2half(sc[d]);
    }
    __syncthreads();

    int aRow = lane & 15, aKo = (lane >> 4) << 3;
    int bRow = (lane & 7) + ((lane >> 4) << 3);
    int bKo = ((lane >> 3) & 1) << 3;
    {
        float acc[2][8][4];
        #pragma unroll
        for (int i = 0; i < 2; i++)
            #pragma unroll
            for (int j = 0; j < 8; j++)
                #pragma unroll
                for (int k = 0; k < 4; k++) acc[i][j][k] = 0.f;
        #pragma unroll
        for (int ks = 0; ks < 4; ks++) {
            uint32_t aq[2][4], bf[8][2];
            #pragma unroll
            for (int mt = 0; mt < 2; mt++)
                ldsm4(aq[mt], sb + S2_PH +
                      (uint32_t)((w*32 + mt*16 + aRow) * 72 + ks*16 + aKo) * 2);
            #pragma unroll
            for (int g = 0; g < 4; g++) {
                uint32_t r[4];
                ldsm4(r, sb + S2_VT + (uint32_t)((g*16 + bRow) * 72 + ks*16 + bKo) * 2);
                bf[g*2][0] = r[0]; bf[g*2][1] = r[1];
                bf[g*2+1][0] = r[2]; bf[g*2+1][1] = r[3];
            }
            #pragma unroll
            for (int mt = 0; mt < 2; mt++)
                #pragma unroll
                for (int nt = 0; nt < 8; nt++) mma16816(acc[mt][nt], aq[mt], bf[nt]);
        }
        #pragma unroll
        for (int mt = 0; mt < 2; mt++) {
            int r0 = w*32 + mt*16 + (lane >> 2);
            float inv0 = Linv[r0], inv1 = Linv[r0 + 8];
            float* O0 = g_VVV + ((size_t)bh * Sq + s0 + r0) * 64;
            float* O1 = g_VVV + ((size_t)bh * Sq + s0 + r0 + 8) * 64;
            #pragma unroll
            for (int nt = 0; nt < 8; nt++) {
                int c = nt*8 + (lane & 3) * 2;
                *(float2*)(O0 + c) = make_float2(acc[mt][nt][0] * inv0, acc[mt][nt][1] * inv0);
                *(float2*)(O1 + c) = make_float2(acc[mt][nt][2] * inv1, acc[mt][nt][3] * inv1);
            }
        }
    }
}

// ---------------------------------------------------------------------------
// LayerNorm (1024), vectorized float4.
// x = in1 + res.  sel=0: in1=g_VVV, res=Xq, out=g_O1 + fp16 g_Ah.
//                 sel=1: in1=g_O2,  res=g_O1, out=d_out.
// ---------------------------------------------------------------------------
__global__ void k_ln(const float* __restrict__ rese, const float* __restrict__ g,
                     const float* __restrict__ bb, float* __restrict__ oute, int sel) {
    const float* in1 = sel ? g_O2 : g_VVV;
    const float* res = sel ? g_O1 : rese;
    float* out = sel ? oute : g_O1;
    __shared__ float sm1[8];
    __shared__ float sm2[8];
    size_t base = (size_t)blockIdx.x * 1024;
    int t = threadIdx.x;
    int c = t * 4;
    float4 v = *(const float4*)(in1 + base + c);
    float4 r = *(const float4*)(res + base + c);
    v.x += r.x; v.y += r.y; v.z += r.z; v.w += r.w;
    float sum = v.x + v.y + v.z + v.w;
    #pragma unroll
    for (int o = 16; o > 0; o >>= 1) sum += __shfl_xor_sync(0xffffffffu, sum, o);
    if ((t & 31) == 0) sm1[t >> 5] = sum;
    __syncthreads();
    sum = 0.f;
    #pragma unroll
    for (int i = 0; i < 8; i++) sum += sm1[i];
    float mean = sum * (1.f / 1024.f);
    float dx = v.x - mean, dy = v.y - mean, dz = v.z - mean, dw = v.w - mean;
    float sq = dx*dx + dy*dy + dz*dz + dw*dw;
    #pragma unroll
    for (int o = 16; o > 0; o >>= 1) sq += __shfl_xor_sync(0xffffffffu, sq, o);
    if ((t & 31) == 0) sm2[t >> 5] = sq;
    __syncthreads();
    sq = 0.f;
    #pragma unroll
    for (int i = 0; i < 8; i++) sq += sm2[i];
    float rstd = rsqrtf(sq * (1.f / 1024.f) + 1e-5f);
    float4 gv = *(const float4*)(g + c);
    float4 bv = *(const float4*)(bb + c);
    float4 o4;
    o4.x = dx * rstd * gv.x + bv.x;
    o4.y = dy * rstd * gv.y + bv.y;
    o4.z = dz * rstd * gv.z + bv.z;
    o4.w = dw * rstd * gv.w + bv.w;
    *(float4*)(out + base + c) = o4;
    if (sel == 0) {
        *(__half2*)(g_Ah + base + c)     = __floats2half2_rn(o4.x, o4.y);
        *(__half2*)(g_Ah + base + c + 2) = __floats2half2_rn(o4.z, o4.w);
    }
}

// ===========================================================================
// Host side — single stream.
// ===========================================================================
extern "C" void kernel_launch(void* const* d_in, const int* in_sizes, int n_in,
                              void* d_out, int out_size) {
    const float* Xq  = (const float*)d_in[0];
    const float* Xk  = (const float*)d_in[1];
    const float* Xv  = (const float*)d_in[2];
    const float* Wq1 = (const float*)d_in[3];
    const float* Wq2 = (const float*)d_in[4];
    const float* Wk1 = (const float*)d_in[5];
    const float* Wk2 = (const float*)d_in[6];
    const float* Wv  = (const float*)d_in[7];
    const float* Wfc = (const float*)d_in[8];
    const float* Am  = (const float*)d_in[9];
    const float* lng = (const float*)d_in[10];
    const float* lnb = (const float*)d_in[11];
    float* out = (float*)d_out;
    size_t attn_off = (out_size > OUT_MAIN) ? (size_t)(out_size - OUT_MAIN) : 0;
    float* attn = out + attn_off;

    void *pO2, *pVV, *pL, *pTq, *pTk;
    cudaGetSymbolAddress(&pO2, g_O2);
    cudaGetSymbolAddress(&pVV, g_VV);
    cudaGetSymbolAddress(&pL,  g_L);
    cudaGetSymbolAddress(&pTq, g_Tq);
    cudaGetSymbolAddress(&pTk, g_Tk);

    cudaFuncSetAttribute(k_hgemm,  cudaFuncAttributeMaxDynamicSharedMemorySize, HG_SMEM);
    cudaFuncSetAttribute(k_proj1,  cudaFuncAttributeMaxDynamicSharedMemorySize, P1_SMEM);
    cudaFuncSetAttribute(k_stage2, cudaFuncAttributeMaxDynamicSharedMemorySize, S2_SMEM);

    k_half<<<16384, 256>>>(Xv);
    k_halfT<<<dim3(32, 32), dim3(32, 8)>>>(Wv, 0);
    k_prepW<<<16, 256>>>(Wq2, Wk2, Am);
    cudaMemsetAsync(pTq, 0, (size_t)Mrows * 32 * sizeof(float));
    cudaMemsetAsync(pTk, 0, (size_t)Mrows * 32 * sizeof(float));

    k_hgemm<<<dim3(8, 128), 512, HG_SMEM>>>(nullptr, 0);    // V -> g_Vh

    k_proj1<<<dim3(4, 256), 256, P1_SMEM>>>(Xq, Wq1, 0);
    k_proj1<<<dim3(4, 256), 256, P1_SMEM>>>(Xk, Wk1, 1);

    cudaMemsetAsync(pL,  0, (size_t)BHn * DHq * sizeof(float));
    cudaMemsetAsync(pVV, 0, (size_t)BHn * DHq * DHq * sizeof(float));
    k_s1exp<<<dim3(32, 128), 256>>>(attn);                  // raw E + row sums
    k_vv<<<dim3(4, 128), 256>>>(attn);                      // normalize + VV
    k_stage2<<<dim3(16, 128), 128, S2_SMEM>>>();
    k_ln<<<16384, 256>>>(Xq, lng, lnb, nullptr, 0);         // out1 + fp16

    k_halfT<<<dim3(32, 32), dim3(32, 8)>>>(Wfc, 1);
    k_hgemm<<<dim3(8, 128), 512, HG_SMEM>>>((float*)pO2, 1);// out2 = out1@Wfc
    k_ln<<<16384, 256>>>(nullptr, lng, lnb, out, 1);        // out = LN(out2+out1)
}